// round 16
// baseline (speedup 1.0000x reference)
#include <cuda_runtime.h>
#include <cuda_fp16.h>
#include <math.h>
#include <stdint.h>

#define NB 2
#define NH 12
#define ND 16
#define NS 512
#define HD 64
#define HID 768
#define NT 545
#define NTB 8225
#define MTOT (NB*NTB)      // 16450
#define ATT_SCALE 0.125f
#define LOG2E 1.44269504f

// fp16 operands: inputs A, weights W, projected Q/K/V (Q pre-scaled by ATT_SCALE*LOG2E)
__device__ __half g_A[(size_t)MTOT * HID];
__device__ __half g_W[(size_t)3 * HID * HID];
__device__ __half g_Qp[(size_t)MTOT * HID];
__device__ __half g_Kp[(size_t)MTOT * HID];
__device__ __half g_Vp[(size_t)MTOT * HID];

// ---------------------------------------------------------------------------
// helpers
// ---------------------------------------------------------------------------
__device__ __forceinline__ uint32_t smem_u32(const void* p) {
    uint32_t a;
    asm("{ .reg .u64 t; cvta.to.shared.u64 t, %1; cvt.u32.u64 %0, t; }" : "=r"(a) : "l"(p));
    return a;
}

__device__ __forceinline__ uint32_t pk2h(float a, float b) {
    __half2 h = __floats2half2_rn(a, b);
    return *(uint32_t*)&h;
}

__device__ __forceinline__ uint32_t h2ex2(uint32_t x) {
    uint32_t r;
    asm("ex2.approx.f16x2 %0, %1;" : "=r"(r) : "r"(x));
    return r;
}

__device__ __forceinline__ uint32_t hadd2u(uint32_t a, uint32_t b) {
    uint32_t r;
    asm("add.rn.f16x2 %0, %1, %2;" : "=r"(r) : "r"(a), "r"(b));
    return r;
}

__device__ __forceinline__ float2 h22f2(uint32_t h) {
    __half2 hh = *(__half2*)&h;
    return __half22float2(hh);
}

#define LDSM_X4(r0, r1, r2, r3, addr) \
    asm volatile("ldmatrix.sync.aligned.m8n8.x4.shared.b16 {%0,%1,%2,%3}, [%4];" \
        : "=r"(r0), "=r"(r1), "=r"(r2), "=r"(r3) : "r"(addr))

#define LDSM_X4_T(r0, r1, r2, r3, addr) \
    asm volatile("ldmatrix.sync.aligned.m8n8.x4.trans.shared.b16 {%0,%1,%2,%3}, [%4];" \
        : "=r"(r0), "=r"(r1), "=r"(r2), "=r"(r3) : "r"(addr))

#define MMA_F16(d, a, b0, b1) \
    asm volatile("mma.sync.aligned.m16n8k16.row.col.f32.f16.f16.f32 " \
        "{%0,%1,%2,%3},{%4,%5,%6,%7},{%8,%9},{%0,%1,%2,%3};" \
        : "+f"((d)[0]), "+f"((d)[1]), "+f"((d)[2]), "+f"((d)[3]) \
        : "r"((a)[0]), "r"((a)[1]), "r"((a)[2]), "r"((a)[3]), "r"(b0), "r"(b1))

// ---------------------------------------------------------------------------
// Conversion: gather A rows (cls/query/doc) AND weights -> fp16, one launch.
// ---------------------------------------------------------------------------
#define NA_VEC (MTOT * (HID / 8))            // 1579200
#define NW_VEC (3 * HID * (HID / 8))         // 221184

__global__ __launch_bounds__(256) void convAW_kernel(
    const float* __restrict__ cls, const float* __restrict__ qry,
    const float* __restrict__ doc,
    const float* __restrict__ Wq, const float* __restrict__ Wk,
    const float* __restrict__ Wv)
{
    int gid = blockIdx.x * 256 + threadIdx.x;
    const float* src;
    __half* dst;
    if (gid < NA_VEC) {
        int m = gid / (HID / 8);
        int c8 = (gid % (HID / 8)) * 8;
        int bb = (m >= NTB) ? 1 : 0;
        int u = m - bb * NTB;
        if (u == 0)      src = cls + (size_t)bb * HID + c8;
        else if (u < 33) src = qry + (size_t)(bb * 32 + (u - 1)) * HID + c8;
        else             src = doc + ((size_t)bb * (ND * NS) + (u - 33)) * HID + c8;
        dst = g_A + (size_t)m * HID + c8;
    } else if (gid < NA_VEC + NW_VEC) {
        int wg = gid - NA_VEC;
        int z = wg / (HID * (HID / 8));
        int rem = wg - z * (HID * (HID / 8));
        int off8 = rem * 8;
        src = ((z == 0) ? Wq : (z == 1) ? Wk : Wv) + off8;
        dst = g_W + (size_t)z * HID * HID + off8;
    } else {
        return;
    }
    float4 x0 = *(const float4*)(src);
    float4 x1 = *(const float4*)(src + 4);
    uint4 v = make_uint4(pk2h(x0.x, x0.y), pk2h(x0.z, x0.w),
                         pk2h(x1.x, x1.y), pk2h(x1.z, x1.w));
    *(uint4*)dst = v;
}

// ---------------------------------------------------------------------------
// fp16 mma.sync projection GEMM. 3-stage cp.async ring, distance-2 prefetch,
// ONE sync per K-chunk (wait -> sync -> issue c+2 -> compute). 2 CTAs/SM.
// 128x128 CTA tile, 8 warps (4x2), warp tile 32x64, K-chunk 64.
// (R11-proven configuration.)
// ---------------------------------------------------------------------------
#define P_PITCH 144
#define P_MATB  18432
#define P_STAGE 36864
#define P_SMEM  110592          // 3 stages

__device__ __forceinline__ void proj_load_chunk(
    char* smem, int stage, int m0, int n0, int kk,
    const __half* __restrict__ W, int tid)
{
    char* base = smem + stage * P_STAGE;
    #pragma unroll
    for (int it = 0; it < 8; it++) {
        int idx = tid + it * 256;
        int mat  = idx >> 10;
        int r    = (idx >> 3) & 127;
        int slot = idx & 7;
        uint32_t dst = smem_u32(base + mat * P_MATB + r * P_PITCH + slot * 16);
        const void* src;
        int sz = 16;
        if (mat == 0) {
            int m = m0 + r;
            if (m >= MTOT) { m = 0; sz = 0; }
            src = g_A + (size_t)m * HID + kk + slot * 8;
        } else {
            src = W + (size_t)(n0 + r) * HID + kk + slot * 8;
        }
        asm volatile("cp.async.cg.shared.global [%0], [%1], 16, %2;"
                     :: "r"(dst), "l"(src), "r"(sz));
    }
    asm volatile("cp.async.commit_group;" ::: "memory");
}

__global__ __launch_bounds__(256, 2) void mma_proj_kernel(
    const float* __restrict__ bq, const float* __restrict__ bk,
    const float* __restrict__ bv)
{
    extern __shared__ char smem[];
    const int tid  = threadIdx.x;
    const int wid  = tid >> 5;
    const int lane = tid & 31;
    const int n0 = blockIdx.x * 128;
    const int m0 = blockIdx.y * 128;
    const int z  = blockIdx.z;

    const __half* W = g_W + (size_t)z * HID * HID;
    __half* outp = (z == 0) ? g_Qp : (z == 1) ? g_Kp : g_Vp;
    const float* bias = (z == 0) ? bq : (z == 1) ? bk : bv;
    const float osc = (z == 0) ? (ATT_SCALE * LOG2E) : 1.0f;

    const int warp_m = (wid & 3) * 32;
    const int warp_n = (wid >> 2) * 64;

    float acc[2][8][4];
    #pragma unroll
    for (int i = 0; i < 2; i++)
        #pragma unroll
        for (int j = 0; j < 8; j++)
            #pragma unroll
            for (int v = 0; v < 4; v++) acc[i][j][v] = 0.f;

    const int lrow  = lane & 15;
    const int lhalf = (lane >> 4) & 1;
    const uint32_t sbase = smem_u32(smem);

    proj_load_chunk(smem, 0, m0, n0, 0, W, tid);
    proj_load_chunk(smem, 1, m0, n0, 64, W, tid);

    for (int c = 0; c < 12; c++) {
        if (c == 11) {
            asm volatile("cp.async.wait_group 0;" ::: "memory");
        } else {
            asm volatile("cp.async.wait_group 1;" ::: "memory");
        }
        __syncthreads();
        if (c + 2 < 12)
            proj_load_chunk(smem, (c + 2) % 3, m0, n0, (c + 2) * 64, W, tid);

        const uint32_t sb = sbase + (c % 3) * P_STAGE;
        #pragma unroll
        for (int ks = 0; ks < 4; ks++) {
            const int kb = ks * 32 + lhalf * 16;
            uint32_t af[2][4];
            #pragma unroll
            for (int mi = 0; mi < 2; mi++) {
                uint32_t ra = sb + (warp_m + mi * 16 + lrow) * P_PITCH + kb;
                LDSM_X4(af[mi][0], af[mi][1], af[mi][2], af[mi][3], ra);
            }
            #pragma unroll
            for (int nj = 0; nj < 4; nj++) {
                uint32_t wf[4];
                uint32_t rw = sb + P_MATB + (warp_n + nj * 16 + lrow) * P_PITCH + kb;
                LDSM_X4(wf[0], wf[1], wf[2], wf[3], rw);
                #pragma unroll
                for (int mi = 0; mi < 2; mi++) {
                    MMA_F16(acc[mi][2 * nj + 0], af[mi], wf[0], wf[2]);
                    MMA_F16(acc[mi][2 * nj + 1], af[mi], wf[1], wf[3]);
                }
            }
        }
    }

    const int qr = lane >> 2;
    const int qc = (lane & 3) * 2;
    #pragma unroll
    for (int jj = 0; jj < 8; jj++) {
        int cc = n0 + warp_n + jj * 8 + qc;
        float bx = bias[cc], by = bias[cc + 1];
        #pragma unroll
        for (int mi = 0; mi < 2; mi++) {
            const float* a4 = acc[mi][jj];
            int r0 = m0 + warp_m + mi * 16 + qr;
            if (r0 < MTOT) {
                *(uint32_t*)(outp + (size_t)r0 * HID + cc) =
                    pk2h((a4[0] + bx) * osc, (a4[1] + by) * osc);
            }
            int r1 = r0 + 8;
            if (r1 < MTOT) {
                *(uint32_t*)(outp + (size_t)r1 * HID + cc) =
                    pk2h((a4[2] + bx) * osc, (a4[3] + by) * osc);
            }
        }
    }
}

// ---------------------------------------------------------------------------
// fp16 mma.sync flash attention, max-free f16x2 softmax in exp2 domain.
// CTA: 64 q-rows, 4 warps, 128 threads. 64-key tiles, 2-stage cp.async ring,
// race-free (wait -> sync -> issue -> compute). Q via LDG into fragments.
// NOW 5 CTAs/SM (102-reg cap; smem 38KB x 5 = 190KB <= 228KB).
// ---------------------------------------------------------------------------
#define A_PITCH 144
#define A_KVMAT 9216            // 64*144
#define A_STAGE 18432           // K + V
#define A_MASK  36864           // 288 half2 = 1152 B
#define A_SMEM  38016
#define NKT 9                   // ceil(545/64)
#define A_THREADS 128

__device__ __forceinline__ void attn_load_kv(
    char* smem, int st, int b, int d, int h, int kt, int tid)
{
    char* base = smem + st * A_STAGE;
    #pragma unroll
    for (int it = 0; it < 8; it++) {
        int idx = tid + it * A_THREADS;  // 0..1023
        int mat  = idx >> 9;             // 0=K, 1=V
        int r    = (idx >> 3) & 63;
        int slot = idx & 7;
        int t = kt * 64 + r;
        int sz = 16, u = 0;
        if (t < NT) u = (t < 33) ? t : 33 + d * NS + (t - 33);
        else sz = 0;
        const __half* A = (mat == 0) ? g_Kp : g_Vp;
        const void* src = A + ((size_t)b * NTB + u) * HID + h * HD + slot * 8;
        uint32_t dst = smem_u32(base + mat * A_KVMAT + r * A_PITCH + slot * 16);
        asm volatile("cp.async.cg.shared.global [%0], [%1], 16, %2;"
                     :: "r"(dst), "l"(src), "r"(sz));
    }
    asm volatile("cp.async.commit_group;" ::: "memory");
}

__global__ __launch_bounds__(A_THREADS, 5) void attn_mma_kernel(
    const float* __restrict__ qmask, const float* __restrict__ dmask,
    float* __restrict__ out)
{
    extern __shared__ char smem[];
    const int tid  = threadIdx.x;
    const int wid  = tid >> 5;
    const int lane = tid & 31;
    const int lrow  = lane & 15;
    const int lhalf = lane >> 4;
    const int qt = blockIdx.x;           // 0..8 (64-row q tiles)
    const int h  = blockIdx.y;
    const int b  = blockIdx.z >> 4;
    const int d  = blockIdx.z & 15;
    const int warp_q = wid * 16;
    const uint32_t sbase = smem_u32(smem);

    // masks: preload as packed half2 (log2e-scaled); -1e30 -> -inf -> exp 0
    for (int i = tid; i < NKT * 32; i += A_THREADS) {
        int t0 = 2 * i, t1 = 2 * i + 1;
        float m0 = -1e30f, m1 = -1e30f;
        if (t0 < NT) {
            if (t0 == 0)      m0 = 0.f;
            else if (t0 < 33) m0 = qmask[b * 32 + (t0 - 1)] * LOG2E;
            else              m0 = dmask[((size_t)b * ND + d) * NS + (t0 - 33)] * LOG2E;
        }
        if (t1 < NT) {
            if (t1 < 33)      m1 = qmask[b * 32 + (t1 - 1)] * LOG2E;
            else              m1 = dmask[((size_t)b * ND + d) * NS + (t1 - 33)] * LOG2E;
        }
        ((uint32_t*)(smem + A_MASK))[i] = pk2h(m0, m1);
    }

    attn_load_kv(smem, 0, b, d, h, 0, tid);   // first KV tile

    // Q fragments straight from gmem (A-fragment layout)
    uint32_t qf[4][4];
    {
        int r0t = qt * 64 + warp_q + (lane >> 2);
        int r1t = r0t + 8;
        int u0 = 0, u1 = 0;
        if (r0t < NT) u0 = (r0t < 33) ? r0t : 33 + d * NS + (r0t - 33);
        if (r1t < NT) u1 = (r1t < 33) ? r1t : 33 + d * NS + (r1t - 33);
        const __half* q0p = g_Qp + ((size_t)b * NTB + u0) * HID + h * HD + (lane & 3) * 2;
        const __half* q1p = g_Qp + ((size_t)b * NTB + u1) * HID + h * HD + (lane & 3) * 2;
        #pragma unroll
        for (int ks = 0; ks < 4; ks++) {
            qf[ks][0] = *(const uint32_t*)(q0p + ks * 16);
            qf[ks][1] = *(const uint32_t*)(q1p + ks * 16);
            qf[ks][2] = *(const uint32_t*)(q0p + ks * 16 + 8);
            qf[ks][3] = *(const uint32_t*)(q1p + ks * 16 + 8);
        }
    }

    float l0 = 0.f, l1 = 0.f;
    float oacc[8][4];
    #pragma unroll
    for (int i = 0; i < 8; i++)
        #pragma unroll
        for (int v = 0; v < 4; v++) oacc[i][v] = 0.f;

    const uint32_t* maskh2 = (const uint32_t*)(smem + A_MASK);

    for (int kt = 0; kt < NKT; kt++) {
        asm volatile("cp.async.wait_group 0;" ::: "memory");
        __syncthreads();
        if (kt + 1 < NKT)
            attn_load_kv(smem, (kt + 1) & 1, b, d, h, kt + 1, tid);

        const uint32_t sb = sbase + (kt & 1) * A_STAGE;
        const uint32_t* mrow = maskh2 + kt * 32;

        // ---- S = Q K^T (log2 domain) ----
        float sacc[8][4];
        #pragma unroll
        for (int i = 0; i < 8; i++)
            #pragma unroll
            for (int v = 0; v < 4; v++) sacc[i][v] = 0.f;

        #pragma unroll
        for (int ks = 0; ks < 4; ks++) {
            #pragma unroll
            for (int nj = 0; nj < 4; nj++) {
                uint32_t kf[4];
                uint32_t ra = sb + (nj * 16 + lrow) * A_PITCH + ks * 32 + lhalf * 16;
                LDSM_X4(kf[0], kf[1], kf[2], kf[3], ra);
                MMA_F16(sacc[2*nj + 0], qf[ks], kf[0], kf[2]);
                MMA_F16(sacc[2*nj + 1], qf[ks], kf[1], kf[3]);
            }
        }

        // ---- max-free f16x2 softmax: pf = 2^(s + m) ----
        uint32_t pf[4][4];
        #pragma unroll
        for (int kj = 0; kj < 4; kj++) {
            uint32_t mha = mrow[kj * 8 + (lane & 3)];
            uint32_t mhb = mrow[kj * 8 + 4 + (lane & 3)];
            uint32_t s0 = pk2h(sacc[2*kj][0],   sacc[2*kj][1]);
            uint32_t s1 = pk2h(sacc[2*kj][2],   sacc[2*kj][3]);
            uint32_t s2 = pk2h(sacc[2*kj+1][0], sacc[2*kj+1][1]);
            uint32_t s3 = pk2h(sacc[2*kj+1][2], sacc[2*kj+1][3]);
            pf[kj][0] = h2ex2(hadd2u(s0, mha));
            pf[kj][1] = h2ex2(hadd2u(s1, mha));
            pf[kj][2] = h2ex2(hadd2u(s2, mhb));
            pf[kj][3] = h2ex2(hadd2u(s3, mhb));
            float2 f0 = h22f2(hadd2u(pf[kj][0], pf[kj][2]));
            float2 f1 = h22f2(hadd2u(pf[kj][1], pf[kj][3]));
            l0 += f0.x + f0.y;
            l1 += f1.x + f1.y;
        }

        // ---- O += P V, V via ldmatrix.trans ----
        #pragma unroll
        for (int kj = 0; kj < 4; kj++) {
            #pragma unroll
            for (int nd = 0; nd < 4; nd++) {
                uint32_t vf[4];
                uint32_t ra = sb + A_KVMAT + (kj * 16 + lrow) * A_PITCH
                            + nd * 32 + lhalf * 16;
                LDSM_X4_T(vf[0], vf[1], vf[2], vf[3], ra);
                MMA_F16(oacc[2*nd + 0], pf[kj], vf[0], vf[1]);
                MMA_F16(oacc[2*nd + 1], pf[kj], vf[2], vf[3]);
            }
        }
    }

    // final row-sum reduce across quad
    l0 += __shfl_xor_sync(0xffffffffu, l0, 1);
    l0 += __shfl_xor_sync(0xffffffffu, l0, 2);
    l1 += __shfl_xor_sync(0xffffffffu, l1, 1);
    l1 += __shfl_xor_sync(0xffffffffu, l1, 2);

    // epilogue
    const int q2 = (lane & 3) * 2;
    int t0 = qt * 64 + warp_q + (lane >> 2);
    int t1 = t0 + 8;
    float inv0 = 1.f / l0, inv1 = 1.f / l1;
    #pragma unroll
    for (int nd = 0; nd < 8; nd++) {
        int col = h * HD + nd * 8 + q2;
        if (t0 < NT) {
            float2 v = make_float2(oacc[nd][0] * inv0, oacc[nd][1] * inv0);
            *(float2*)(out + ((size_t)(b * ND + d) * NT + t0) * HID + col) = v;
        }
        if (t1 < NT) {
            float2 v = make_float2(oacc[nd][2] * inv1, oacc[nd][3] * inv1);
            *(float2*)(out + ((size_t)(b * ND + d) * NT + t1) * HID + col) = v;
        }
    }
}

extern "C" void kernel_launch(void* const* d_in, const int* in_sizes, int n_in,
                              void* d_out, int out_size)
{
    const float* cls   = (const float*)d_in[0];
    const float* query = (const float*)d_in[1];
    const float* doc   = (const float*)d_in[2];
    const float* qmask = (const float*)d_in[3];
    const float* dmask = (const float*)d_in[4];
    const float* Wq    = (const float*)d_in[5];
    const float* bq    = (const float*)d_in[6];
    const float* Wk    = (const float*)d_in[7];
    const float* bk    = (const float*)d_in[8];
    const float* Wv    = (const float*)d_in[9];
    const float* bv    = (const float*)d_in[10];
    float* out = (float*)d_out;

    static int attr_set = 0;
    if (!attr_set) {
        cudaFuncSetAttribute(mma_proj_kernel,
                             cudaFuncAttributeMaxDynamicSharedMemorySize, P_SMEM);
        cudaFuncSetAttribute(attn_mma_kernel,
                             cudaFuncAttributeMaxDynamicSharedMemorySize, A_SMEM);
        attr_set = 1;
    }

    convAW_kernel<<<(NA_VEC + NW_VEC + 255) / 256, 256>>>(cls, query, doc, Wq, Wk, Wv);

    dim3 gproj(HID / 128, (MTOT + 127) / 128, 3);   // (6, 129, 3)
    mma_proj_kernel<<<gproj, 256, P_SMEM>>>(bq, bk, bv);

    dim3 gattn((NT + 63) / 64, NH, NB * ND);        // (9, 12, 32)
    attn_mma_kernel<<<gattn, A_THREADS, A_SMEM>>>(qmask, dmask, out);
}

// round 17
// speedup vs baseline: 1.0121x; 1.0121x over previous
#include <cuda_runtime.h>
#include <cuda_fp16.h>
#include <math.h>
#include <stdint.h>

#define NB 2
#define NH 12
#define ND 16
#define NS 512
#define HD 64
#define HID 768
#define NT 545
#define NTB 8225
#define MTOT (NB*NTB)      // 16450
#define ATT_SCALE 0.125f
#define LOG2E 1.44269504f

// fp16 operands: inputs A, weights W, projected Q/K/V (Q pre-scaled by ATT_SCALE*LOG2E)
__device__ __half g_A[(size_t)MTOT * HID];
__device__ __half g_W[(size_t)3 * HID * HID];
__device__ __half g_Qp[(size_t)MTOT * HID];
__device__ __half g_Kp[(size_t)MTOT * HID];
__device__ __half g_Vp[(size_t)MTOT * HID];

// ---------------------------------------------------------------------------
// helpers
// ---------------------------------------------------------------------------
__device__ __forceinline__ uint32_t smem_u32(const void* p) {
    uint32_t a;
    asm("{ .reg .u64 t; cvta.to.shared.u64 t, %1; cvt.u32.u64 %0, t; }" : "=r"(a) : "l"(p));
    return a;
}

__device__ __forceinline__ uint32_t pk2h(float a, float b) {
    __half2 h = __floats2half2_rn(a, b);
    return *(uint32_t*)&h;
}

__device__ __forceinline__ uint32_t h2ex2(uint32_t x) {
    uint32_t r;
    asm("ex2.approx.f16x2 %0, %1;" : "=r"(r) : "r"(x));
    return r;
}

__device__ __forceinline__ uint32_t hadd2u(uint32_t a, uint32_t b) {
    uint32_t r;
    asm("add.rn.f16x2 %0, %1, %2;" : "=r"(r) : "r"(a), "r"(b));
    return r;
}

__device__ __forceinline__ float2 h22f2(uint32_t h) {
    __half2 hh = *(__half2*)&h;
    return __half22float2(hh);
}

#define LDSM_X4(r0, r1, r2, r3, addr) \
    asm volatile("ldmatrix.sync.aligned.m8n8.x4.shared.b16 {%0,%1,%2,%3}, [%4];" \
        : "=r"(r0), "=r"(r1), "=r"(r2), "=r"(r3) : "r"(addr))

#define LDSM_X4_T(r0, r1, r2, r3, addr) \
    asm volatile("ldmatrix.sync.aligned.m8n8.x4.trans.shared.b16 {%0,%1,%2,%3}, [%4];" \
        : "=r"(r0), "=r"(r1), "=r"(r2), "=r"(r3) : "r"(addr))

#define MMA_F16(d, a, b0, b1) \
    asm volatile("mma.sync.aligned.m16n8k16.row.col.f32.f16.f16.f32 " \
        "{%0,%1,%2,%3},{%4,%5,%6,%7},{%8,%9},{%0,%1,%2,%3};" \
        : "+f"((d)[0]), "+f"((d)[1]), "+f"((d)[2]), "+f"((d)[3]) \
        : "r"((a)[0]), "r"((a)[1]), "r"((a)[2]), "r"((a)[3]), "r"(b0), "r"(b1))

// ---------------------------------------------------------------------------
// Conversion: gather A rows (cls/query/doc) AND weights -> fp16, one launch.
// ---------------------------------------------------------------------------
#define NA_VEC (MTOT * (HID / 8))            // 1579200
#define NW_VEC (3 * HID * (HID / 8))         // 221184

__global__ __launch_bounds__(256) void convAW_kernel(
    const float* __restrict__ cls, const float* __restrict__ qry,
    const float* __restrict__ doc,
    const float* __restrict__ Wq, const float* __restrict__ Wk,
    const float* __restrict__ Wv)
{
    int gid = blockIdx.x * 256 + threadIdx.x;
    const float* src;
    __half* dst;
    if (gid < NA_VEC) {
        int m = gid / (HID / 8);
        int c8 = (gid % (HID / 8)) * 8;
        int bb = (m >= NTB) ? 1 : 0;
        int u = m - bb * NTB;
        if (u == 0)      src = cls + (size_t)bb * HID + c8;
        else if (u < 33) src = qry + (size_t)(bb * 32 + (u - 1)) * HID + c8;
        else             src = doc + ((size_t)bb * (ND * NS) + (u - 33)) * HID + c8;
        dst = g_A + (size_t)m * HID + c8;
    } else if (gid < NA_VEC + NW_VEC) {
        int wg = gid - NA_VEC;
        int z = wg / (HID * (HID / 8));
        int rem = wg - z * (HID * (HID / 8));
        int off8 = rem * 8;
        src = ((z == 0) ? Wq : (z == 1) ? Wk : Wv) + off8;
        dst = g_W + (size_t)z * HID * HID + off8;
    } else {
        return;
    }
    float4 x0 = *(const float4*)(src);
    float4 x1 = *(const float4*)(src + 4);
    uint4 v = make_uint4(pk2h(x0.x, x0.y), pk2h(x0.z, x0.w),
                         pk2h(x1.x, x1.y), pk2h(x1.z, x1.w));
    *(uint4*)dst = v;
}

// ---------------------------------------------------------------------------
// fp16 mma.sync projection GEMM. 2-stage cp.async ring, distance-1 prefetch,
// race-free ordering (wait 0 -> sync -> issue c+1 -> compute c). 2 CTAs/SM.
// 128x128 CTA tile, 8 warps (4x2), warp tile 32x64, K-chunk 64.
// ---------------------------------------------------------------------------
#define P_PITCH 144
#define P_MATB  18432
#define P_STAGE 36864
#define P_SMEM  73728           // 2 stages

__device__ __forceinline__ void proj_load_chunk(
    char* smem, int stage, int m0, int n0, int kk,
    const __half* __restrict__ W, int tid)
{
    char* base = smem + stage * P_STAGE;
    #pragma unroll
    for (int it = 0; it < 8; it++) {
        int idx = tid + it * 256;
        int mat  = idx >> 10;
        int r    = (idx >> 3) & 127;
        int slot = idx & 7;
        uint32_t dst = smem_u32(base + mat * P_MATB + r * P_PITCH + slot * 16);
        const void* src;
        int sz = 16;
        if (mat == 0) {
            int m = m0 + r;
            if (m >= MTOT) { m = 0; sz = 0; }
            src = g_A + (size_t)m * HID + kk + slot * 8;
        } else {
            src = W + (size_t)(n0 + r) * HID + kk + slot * 8;
        }
        asm volatile("cp.async.cg.shared.global [%0], [%1], 16, %2;"
                     :: "r"(dst), "l"(src), "r"(sz));
    }
    asm volatile("cp.async.commit_group;" ::: "memory");
}

__global__ __launch_bounds__(256, 2) void mma_proj_kernel(
    const float* __restrict__ bq, const float* __restrict__ bk,
    const float* __restrict__ bv)
{
    extern __shared__ char smem[];
    const int tid  = threadIdx.x;
    const int wid  = tid >> 5;
    const int lane = tid & 31;
    const int n0 = blockIdx.x * 128;
    const int m0 = blockIdx.y * 128;
    const int z  = blockIdx.z;

    const __half* W = g_W + (size_t)z * HID * HID;
    __half* outp = (z == 0) ? g_Qp : (z == 1) ? g_Kp : g_Vp;
    const float* bias = (z == 0) ? bq : (z == 1) ? bk : bv;
    const float osc = (z == 0) ? (ATT_SCALE * LOG2E) : 1.0f;

    const int warp_m = (wid & 3) * 32;
    const int warp_n = (wid >> 2) * 64;

    float acc[2][8][4];
    #pragma unroll
    for (int i = 0; i < 2; i++)
        #pragma unroll
        for (int j = 0; j < 8; j++)
            #pragma unroll
            for (int v = 0; v < 4; v++) acc[i][j][v] = 0.f;

    const int lrow  = lane & 15;
    const int lhalf = (lane >> 4) & 1;
    const uint32_t sbase = smem_u32(smem);

    proj_load_chunk(smem, 0, m0, n0, 0, W, tid);

    for (int c = 0; c < 12; c++) {
        // wait for chunk c's loads, barrier (visibility + WAR), then prefetch
        // chunk c+1 into the other stage, then compute chunk c.
        asm volatile("cp.async.wait_group 0;" ::: "memory");
        __syncthreads();
        if (c + 1 < 12)
            proj_load_chunk(smem, (c + 1) & 1, m0, n0, (c + 1) * 64, W, tid);

        const uint32_t sb = sbase + (c & 1) * P_STAGE;
        #pragma unroll
        for (int ks = 0; ks < 4; ks++) {
            const int kb = ks * 32 + lhalf * 16;
            uint32_t af[2][4];
            #pragma unroll
            for (int mi = 0; mi < 2; mi++) {
                uint32_t ra = sb + (warp_m + mi * 16 + lrow) * P_PITCH + kb;
                LDSM_X4(af[mi][0], af[mi][1], af[mi][2], af[mi][3], ra);
            }
            #pragma unroll
            for (int nj = 0; nj < 4; nj++) {
                uint32_t wf[4];
                uint32_t rw = sb + P_MATB + (warp_n + nj * 16 + lrow) * P_PITCH + kb;
                LDSM_X4(wf[0], wf[1], wf[2], wf[3], rw);
                #pragma unroll
                for (int mi = 0; mi < 2; mi++) {
                    MMA_F16(acc[mi][2 * nj + 0], af[mi], wf[0], wf[2]);
                    MMA_F16(acc[mi][2 * nj + 1], af[mi], wf[1], wf[3]);
                }
            }
        }
    }

    const int qr = lane >> 2;
    const int qc = (lane & 3) * 2;
    #pragma unroll
    for (int jj = 0; jj < 8; jj++) {
        int cc = n0 + warp_n + jj * 8 + qc;
        float bx = bias[cc], by = bias[cc + 1];
        #pragma unroll
        for (int mi = 0; mi < 2; mi++) {
            const float* a4 = acc[mi][jj];
            int r0 = m0 + warp_m + mi * 16 + qr;
            if (r0 < MTOT) {
                *(uint32_t*)(outp + (size_t)r0 * HID + cc) =
                    pk2h((a4[0] + bx) * osc, (a4[1] + by) * osc);
            }
            int r1 = r0 + 8;
            if (r1 < MTOT) {
                *(uint32_t*)(outp + (size_t)r1 * HID + cc) =
                    pk2h((a4[2] + bx) * osc, (a4[3] + by) * osc);
            }
        }
    }
}

// ---------------------------------------------------------------------------
// fp16 mma.sync flash attention, max-free f16x2 softmax in exp2 domain.
// CTA: 64 q-rows, 4 warps, 128 threads, 4 CTAs/SM. 64-key tiles,
// 2-stage cp.async ring, race-free (wait -> sync -> issue -> compute).
// Q via LDG into fragments; masks pre-packed half2. (R11-proven config.)
// ---------------------------------------------------------------------------
#define A_PITCH 144
#define A_KVMAT 9216            // 64*144
#define A_STAGE 18432           // K + V
#define A_MASK  36864           // 288 half2 = 1152 B
#define A_SMEM  38016
#define NKT 9                   // ceil(545/64)
#define A_THREADS 128

__device__ __forceinline__ void attn_load_kv(
    char* smem, int st, int b, int d, int h, int kt, int tid)
{
    char* base = smem + st * A_STAGE;
    #pragma unroll
    for (int it = 0; it < 8; it++) {
        int idx = tid + it * A_THREADS;  // 0..1023
        int mat  = idx >> 9;             // 0=K, 1=V
        int r    = (idx >> 3) & 63;
        int slot = idx & 7;
        int t = kt * 64 + r;
        int sz = 16, u = 0;
        if (t < NT) u = (t < 33) ? t : 33 + d * NS + (t - 33);
        else sz = 0;
        const __half* A = (mat == 0) ? g_Kp : g_Vp;
        const void* src = A + ((size_t)b * NTB + u) * HID + h * HD + slot * 8;
        uint32_t dst = smem_u32(base + mat * A_KVMAT + r * A_PITCH + slot * 16);
        asm volatile("cp.async.cg.shared.global [%0], [%1], 16, %2;"
                     :: "r"(dst), "l"(src), "r"(sz));
    }
    asm volatile("cp.async.commit_group;" ::: "memory");
}

__global__ __launch_bounds__(A_THREADS, 4) void attn_mma_kernel(
    const float* __restrict__ qmask, const float* __restrict__ dmask,
    float* __restrict__ out)
{
    extern __shared__ char smem[];
    const int tid  = threadIdx.x;
    const int wid  = tid >> 5;
    const int lane = tid & 31;
    const int lrow  = lane & 15;
    const int lhalf = lane >> 4;
    const int qt = blockIdx.x;           // 0..8 (64-row q tiles)
    const int h  = blockIdx.y;
    const int b  = blockIdx.z >> 4;
    const int d  = blockIdx.z & 15;
    const int warp_q = wid * 16;
    const uint32_t sbase = smem_u32(smem);

    // masks: preload as packed half2 (log2e-scaled); -1e30 -> -inf -> exp 0
    for (int i = tid; i < NKT * 32; i += A_THREADS) {
        int t0 = 2 * i, t1 = 2 * i + 1;
        float m0 = -1e30f, m1 = -1e30f;
        if (t0 < NT) {
            if (t0 == 0)      m0 = 0.f;
            else if (t0 < 33) m0 = qmask[b * 32 + (t0 - 1)] * LOG2E;
            else              m0 = dmask[((size_t)b * ND + d) * NS + (t0 - 33)] * LOG2E;
        }
        if (t1 < NT) {
            if (t1 < 33)      m1 = qmask[b * 32 + (t1 - 1)] * LOG2E;
            else              m1 = dmask[((size_t)b * ND + d) * NS + (t1 - 33)] * LOG2E;
        }
        ((uint32_t*)(smem + A_MASK))[i] = pk2h(m0, m1);
    }

    attn_load_kv(smem, 0, b, d, h, 0, tid);   // first KV tile

    // Q fragments straight from gmem (A-fragment layout)
    uint32_t qf[4][4];
    {
        int r0t = qt * 64 + warp_q + (lane >> 2);
        int r1t = r0t + 8;
        int u0 = 0, u1 = 0;
        if (r0t < NT) u0 = (r0t < 33) ? r0t : 33 + d * NS + (r0t - 33);
        if (r1t < NT) u1 = (r1t < 33) ? r1t : 33 + d * NS + (r1t - 33);
        const __half* q0p = g_Qp + ((size_t)b * NTB + u0) * HID + h * HD + (lane & 3) * 2;
        const __half* q1p = g_Qp + ((size_t)b * NTB + u1) * HID + h * HD + (lane & 3) * 2;
        #pragma unroll
        for (int ks = 0; ks < 4; ks++) {
            qf[ks][0] = *(const uint32_t*)(q0p + ks * 16);
            qf[ks][1] = *(const uint32_t*)(q1p + ks * 16);
            qf[ks][2] = *(const uint32_t*)(q0p + ks * 16 + 8);
            qf[ks][3] = *(const uint32_t*)(q1p + ks * 16 + 8);
        }
    }

    float l0 = 0.f, l1 = 0.f;
    float oacc[8][4];
    #pragma unroll
    for (int i = 0; i < 8; i++)
        #pragma unroll
        for (int v = 0; v < 4; v++) oacc[i][v] = 0.f;

    const uint32_t* maskh2 = (const uint32_t*)(smem + A_MASK);

    for (int kt = 0; kt < NKT; kt++) {
        asm volatile("cp.async.wait_group 0;" ::: "memory");
        __syncthreads();
        if (kt + 1 < NKT)
            attn_load_kv(smem, (kt + 1) & 1, b, d, h, kt + 1, tid);

        const uint32_t sb = sbase + (kt & 1) * A_STAGE;
        const uint32_t* mrow = maskh2 + kt * 32;

        // ---- S = Q K^T (log2 domain) ----
        float sacc[8][4];
        #pragma unroll
        for (int i = 0; i < 8; i++)
            #pragma unroll
            for (int v = 0; v < 4; v++) sacc[i][v] = 0.f;

        #pragma unroll
        for (int ks = 0; ks < 4; ks++) {
            #pragma unroll
            for (int nj = 0; nj < 4; nj++) {
                uint32_t kf[4];
                uint32_t ra = sb + (nj * 16 + lrow) * A_PITCH + ks * 32 + lhalf * 16;
                LDSM_X4(kf[0], kf[1], kf[2], kf[3], ra);
                MMA_F16(sacc[2*nj + 0], qf[ks], kf[0], kf[2]);
                MMA_F16(sacc[2*nj + 1], qf[ks], kf[1], kf[3]);
            }
        }

        // ---- max-free f16x2 softmax: pf = 2^(s + m) ----
        uint32_t pf[4][4];
        #pragma unroll
        for (int kj = 0; kj < 4; kj++) {
            uint32_t mha = mrow[kj * 8 + (lane & 3)];
            uint32_t mhb = mrow[kj * 8 + 4 + (lane & 3)];
            uint32_t s0 = pk2h(sacc[2*kj][0],   sacc[2*kj][1]);
            uint32_t s1 = pk2h(sacc[2*kj][2],   sacc[2*kj][3]);
            uint32_t s2 = pk2h(sacc[2*kj+1][0], sacc[2*kj+1][1]);
            uint32_t s3 = pk2h(sacc[2*kj+1][2], sacc[2*kj+1][3]);
            pf[kj][0] = h2ex2(hadd2u(s0, mha));
            pf[kj][1] = h2ex2(hadd2u(s1, mha));
            pf[kj][2] = h2ex2(hadd2u(s2, mhb));
            pf[kj][3] = h2ex2(hadd2u(s3, mhb));
            float2 f0 = h22f2(hadd2u(pf[kj][0], pf[kj][2]));
            float2 f1 = h22f2(hadd2u(pf[kj][1], pf[kj][3]));
            l0 += f0.x + f0.y;
            l1 += f1.x + f1.y;
        }

        // ---- O += P V, V via ldmatrix.trans ----
        #pragma unroll
        for (int kj = 0; kj < 4; kj++) {
            #pragma unroll
            for (int nd = 0; nd < 4; nd++) {
                uint32_t vf[4];
                uint32_t ra = sb + A_KVMAT + (kj * 16 + lrow) * A_PITCH
                            + nd * 32 + lhalf * 16;
                LDSM_X4_T(vf[0], vf[1], vf[2], vf[3], ra);
                MMA_F16(oacc[2*nd + 0], pf[kj], vf[0], vf[1]);
                MMA_F16(oacc[2*nd + 1], pf[kj], vf[2], vf[3]);
            }
        }
    }

    // final row-sum reduce across quad
    l0 += __shfl_xor_sync(0xffffffffu, l0, 1);
    l0 += __shfl_xor_sync(0xffffffffu, l0, 2);
    l1 += __shfl_xor_sync(0xffffffffu, l1, 1);
    l1 += __shfl_xor_sync(0xffffffffu, l1, 2);

    // epilogue
    const int q2 = (lane & 3) * 2;
    int t0 = qt * 64 + warp_q + (lane >> 2);
    int t1 = t0 + 8;
    float inv0 = 1.f / l0, inv1 = 1.f / l1;
    #pragma unroll
    for (int nd = 0; nd < 8; nd++) {
        int col = h * HD + nd * 8 + q2;
        if (t0 < NT) {
            float2 v = make_float2(oacc[nd][0] * inv0, oacc[nd][1] * inv0);
            *(float2*)(out + ((size_t)(b * ND + d) * NT + t0) * HID + col) = v;
        }
        if (t1 < NT) {
            float2 v = make_float2(oacc[nd][2] * inv1, oacc[nd][3] * inv1);
            *(float2*)(out + ((size_t)(b * ND + d) * NT + t1) * HID + col) = v;
        }
    }
}

extern "C" void kernel_launch(void* const* d_in, const int* in_sizes, int n_in,
                              void* d_out, int out_size)
{
    const float* cls   = (const float*)d_in[0];
    const float* query = (const float*)d_in[1];
    const float* doc   = (const float*)d_in[2];
    const float* qmask = (const float*)d_in[3];
    const float* dmask = (const float*)d_in[4];
    const float* Wq    = (const float*)d_in[5];
    const float* bq    = (const float*)d_in[6];
    const float* Wk    = (const float*)d_in[7];
    const float* bk    = (const float*)d_in[8];
    const float* Wv    = (const float*)d_in[9];
    const float* bv    = (const float*)d_in[10];
    float* out = (float*)d_out;

    static int attr_set = 0;
    if (!attr_set) {
        cudaFuncSetAttribute(mma_proj_kernel,
                             cudaFuncAttributeMaxDynamicSharedMemorySize, P_SMEM);
        cudaFuncSetAttribute(attn_mma_kernel,
                             cudaFuncAttributeMaxDynamicSharedMemorySize, A_SMEM);
        attr_set = 1;
    }

    convAW_kernel<<<(NA_VEC + NW_VEC + 255) / 256, 256>>>(cls, query, doc, Wq, Wk, Wv);

    dim3 gproj(HID / 128, (MTOT + 127) / 128, 3);   // (6, 129, 3)
    mma_proj_kernel<<<gproj, 256, P_SMEM>>>(bq, bk, bv);

    dim3 gattn((NT + 63) / 64, NH, NB * ND);        // (9, 12, 32)
    attn_mma_kernel<<<gattn, A_THREADS, A_SMEM>>>(qmask, dmask, out);
}